// round 13
// baseline (speedup 1.0000x reference)
#include <cuda_runtime.h>

// Problem constants (fixed by reference: B=16, T=64, C=8, dyadic order 2)
#define NB     16
#define TT     64
#define CC     8
#define NC     63            // coarse increment grid (T-1)
#define NF     252           // fine grid N = (T-1)*4
#define NPAIRS 136           // a <= b pairs (K is symmetric)
#define NIT2   157           // 2-col skewed wavefront iterations

__device__ float g_K[NB * NB];
__device__ int   g_count = 0;

// ---- packed f32x2 helpers (sm_100+) ----
__device__ __forceinline__ unsigned long long pk2(float lo, float hi) {
    unsigned long long r;
    asm("mov.b64 %0, {%1, %2};" : "=l"(r) : "f"(lo), "f"(hi));
    return r;
}
__device__ __forceinline__ void upk2(float& lo, float& hi, unsigned long long v) {
    asm("mov.b64 {%0, %1}, %2;" : "=f"(lo), "=f"(hi) : "l"(v));
}
__device__ __forceinline__ unsigned long long mul2(unsigned long long a, unsigned long long b) {
    unsigned long long r;
    asm("mul.rn.f32x2 %0, %1, %2;" : "=l"(r) : "l"(a), "l"(b));
    return r;
}
__device__ __forceinline__ unsigned long long fma2(unsigned long long a, unsigned long long b,
                                                   unsigned long long c) {
    unsigned long long r;
    asm("fma.rn.f32x2 %0, %1, %2, %3;" : "=l"(r) : "l"(a), "l"(b), "l"(c));
    return r;
}

__global__ __launch_bounds__(128, 1)
void sig_fused_kernel(const float* __restrict__ paths, float* __restrict__ out) {
    // pack[l*65 + idx] = {c1A, -c2A, c1B, -c2B} for lane l (coarse rows 2l, 2l+1):
    //   idx 0 -> identity {1,-1,1,-1}, idx 1..63 -> coarse column idx-1, idx 64 -> identity
    __shared__ float4 pack[32 * 65];                  // 33280 B
    __shared__ float  Gs[33 * 65];                    // 8580 B Gram strip (padded)
    __shared__ __align__(16) float Xa[TT][CC];        // 2 KB
    __shared__ __align__(16) float Xb[TT][CC];        // 2 KB
    __shared__ int    s_last;

    const int tid = threadIdx.x;

    // ---- map block -> ordered pair (a <= b) ----
    int idx = blockIdx.x;
    int a = 0;
    while (idx >= NB - a) { idx -= NB - a; ++a; }
    const int b = a + idx;

    // ---- stage the two paths: X[i][c] = paths[batch][c][i] ----
    const float* pa = paths + a * (CC * TT);
    const float* pb = paths + b * (CC * TT);
    for (int e = tid; e < CC * TT; e += 128) {
        int c = e >> 6;
        int i = e & 63;
        Xa[i][c] = pa[e];
        Xb[i][c] = pb[e];
    }
    __syncthreads();

    // Gram strip: Gs[(u-uBase)*65 + v] = exp(-||Xa_u - Xb_v||^2)
    auto fill_gram = [&](int uBase, int nRows) {
        const float4* xa4 = (const float4*)&Xa[0][0];
        const float4* xb4 = (const float4*)&Xb[0][0];
        for (int e = tid; e < nRows * 64; e += 128) {
            int ur = e >> 6, v = e & 63;
            int u  = uBase + ur;
            float4 a0 = xa4[2 * u], a1 = xa4[2 * u + 1];
            float4 b0 = xb4[2 * v], b1 = xb4[2 * v + 1];
            float d = 0.f, t;
            t = a0.x - b0.x; d = fmaf(t, t, d);
            t = a0.y - b0.y; d = fmaf(t, t, d);
            t = a0.z - b0.z; d = fmaf(t, t, d);
            t = a0.w - b0.w; d = fmaf(t, t, d);
            t = a1.x - b1.x; d = fmaf(t, t, d);
            t = a1.y - b1.y; d = fmaf(t, t, d);
            t = a1.z - b1.z; d = fmaf(t, t, d);
            t = a1.w - b1.w; d = fmaf(t, t, d);
            Gs[ur * 65 + v] = __expf(-d);
        }
    };
    // Pack builder for 16 lanes [lBase, lBase+16); Gs holds rows uBase..uBase+nRows-1.
    // NOTE: stores c2 NEGATED (identity = {1,-1,1,-1}).
    auto build_pack = [&](int lBase, int uBase) {
        for (int e = tid; e < 16 * 65; e += 128) {
            int l  = lBase + e / 65;
            int jc = e - (e / 65) * 65;
            float4 c4 = make_float4(1.f, -1.f, 1.f, -1.f);
            if (jc >= 1 && jc <= 63) {
                int v  = jc - 1;
                int u0 = 2 * l;     if (u0 > NC - 1) u0 = NC - 1;
                int u1 = 2 * l + 1; if (u1 > NC - 1) u1 = NC - 1;
                int r0 = u0 - uBase, r1 = u1 - uBase;
                float A0 = (Gs[(r0+1)*65 + v+1] + Gs[r0*65 + v] - Gs[(r0+1)*65 + v] - Gs[r0*65 + v+1]) * (1.0f/16.0f);
                float A1 = (Gs[(r1+1)*65 + v+1] + Gs[r1*65 + v] - Gs[(r1+1)*65 + v] - Gs[r1*65 + v+1]) * (1.0f/16.0f);
                float q0 = A0 * A0 * (1.0f / 12.0f);
                float q1 = A1 * A1 * (1.0f / 12.0f);
                c4 = make_float4(1.0f + 0.5f * A0 + q0, -(1.0f - q0),
                                 1.0f + 0.5f * A1 + q1, -(1.0f - q1));
            }
            pack[l * 65 + jc] = c4;
        }
    };

    fill_gram(0, 33);
    __syncthreads();
    build_pack(0, 0);
    __syncthreads();
    fill_gram(32, 32);
    __syncthreads();
    build_pack(16, 32);
    __syncthreads();

    // ---- warp 0: barrier-free skewed wavefront, 2 cols/iter, f32x2-packed h-terms ----
    // Lane l owns fine rows 8l+1 .. 8l+8; at iter s it processes cols
    // j0 = 2(s-l)+1, j1 = j0+1 (both in coarse column (s-l)>>1).
    float result = 0.0f;
    if (tid < 32) {
        const int l = tid;
        const float4* packL = &pack[l * 65];

        float p0 = 1.f, p1 = 1.f, p2 = 1.f, p3 = 1.f;
        float p4 = 1.f, p5 = 1.f, p6 = 1.f, p7 = 1.f;   // K[rows][j0-1]
        float topPrev = 1.f;                            // K[8l][j0-1]
        float vlo = 1.f, vhi = 1.f;                     // bottom-row pair for lane l+1

        #pragma unroll 2
        for (int s = 0; s < NIT2; ++s) {
            float tc0 = __shfl_up_sync(0xffffffffu, vlo, 1);  // K[8l][j0]
            float tc1 = __shfl_up_sync(0xffffffffu, vhi, 1);  // K[8l][j1]
            if (l == 0) { tc0 = 1.0f; tc1 = 1.0f; }

            int ci = ((s - l) >> 1) + 1;
            ci = ci < 0 ? 0 : (ci > 64 ? 64 : ci);
            float4 c = packL[ci];          // {c1A, -c2A, c1B, -c2B}

            // broadcast-packed coefficients
            unsigned long long C1A = pk2(c.x, c.x), N2A = pk2(c.y, c.y);
            unsigned long long C1B = pk2(c.z, c.z), N2B = pk2(c.w, c.w);

            // ================= column j0 =================
            // h_r = p_r*c1 + p_{r-1}*(-c2), packed in pairs
            unsigned long long H0 = fma2(pk2(p0, p1), C1A, mul2(pk2(topPrev, p0), N2A));
            unsigned long long H1 = fma2(pk2(p2, p3), C1A, mul2(pk2(p1, p2), N2A));
            unsigned long long H2 = fma2(pk2(p4, p5), C1B, mul2(pk2(p3, p4), N2B));
            unsigned long long H3 = fma2(pk2(p6, p7), C1B, mul2(pk2(p5, p6), N2B));
            float h0, h1, h2, h3, h4, h5, h6, h7;
            upk2(h0, h1, H0); upk2(h2, h3, H1);
            upk2(h4, h5, H2); upk2(h6, h7, H3);
            // serial chain: v_r = fma(v_{r-1}, c1, h_r)
            float v0 = fmaf(tc0, c.x, h0);
            float v1 = fmaf(v0, c.x, h1);
            float v2 = fmaf(v1, c.x, h2);
            float v3 = fmaf(v2, c.x, h3);
            float v4 = fmaf(v3, c.z, h4);
            float v5 = fmaf(v4, c.z, h5);
            float v6 = fmaf(v5, c.z, h6);
            float v7 = fmaf(v6, c.z, h7);

            // ================= column j1 =================
            unsigned long long G0 = fma2(pk2(v0, v1), C1A, mul2(pk2(tc0, v0), N2A));
            unsigned long long G1 = fma2(pk2(v2, v3), C1A, mul2(pk2(v1, v2), N2A));
            unsigned long long G2 = fma2(pk2(v4, v5), C1B, mul2(pk2(v3, v4), N2B));
            unsigned long long G3 = fma2(pk2(v6, v7), C1B, mul2(pk2(v5, v6), N2B));
            float g0, g1, g2, g3, g4, g5, g6, g7;
            upk2(g0, g1, G0); upk2(g2, g3, G1);
            upk2(g4, g5, G2); upk2(g6, g7, G3);
            float w0 = fmaf(tc1, c.x, g0);
            float w1 = fmaf(w0, c.x, g1);
            float w2 = fmaf(w1, c.x, g2);
            float w3 = fmaf(w2, c.x, g3);
            float w4 = fmaf(w3, c.z, g4);
            float w5 = fmaf(w4, c.z, g5);
            float w6 = fmaf(w5, c.z, g6);
            float w7 = fmaf(w6, c.z, g7);

            topPrev = tc1;
            p0 = w0; p1 = w1; p2 = w2; p3 = w3;
            p4 = w4; p5 = w5; p6 = w6; p7 = w7;
            vlo = v7; vhi = w7;
        }
        result = p3;   // lane 31: fine row 252 at column 252 -> K[N][N]
    }

    if (tid == 31) {
        g_K[a * NB + b] = result;
        g_K[b * NB + a] = result;   // symmetry
    }
    __syncthreads();

    // ---- last block to finish does the (16,2) reduction ----
    if (tid == 0) {
        __threadfence();
        int prev = atomicAdd(&g_count, 1);
        s_last = (prev == NPAIRS - 1) ? 1 : 0;
    }
    __syncthreads();
    if (s_last) {
        __threadfence();
        if (tid < NB) {
            float sm = 0.0f;
            #pragma unroll
            for (int bb = 0; bb < NB; ++bb) sm += __ldcg(&g_K[tid * NB + bb]);
            out[2 * tid]     = __ldcg(&g_K[tid * NB + tid]);
            out[2 * tid + 1] = sm * (1.0f / (float)NB);
        }
        if (tid == 0) g_count = 0;   // reset for next graph replay
    }
}

extern "C" void kernel_launch(void* const* d_in, const int* in_sizes, int n_in,
                              void* d_out, int out_size) {
    const float* paths = (const float*)d_in[0];
    sig_fused_kernel<<<NPAIRS, 128>>>(paths, (float*)d_out);
}

// round 14
// speedup vs baseline: 1.2137x; 1.2137x over previous
#include <cuda_runtime.h>

// Problem constants (fixed by reference: B=16, T=64, C=8, dyadic order 2)
#define NB     16
#define TT     64
#define CC     8
#define NC     63            // coarse increment grid (T-1)
#define NF     252           // fine grid N = (T-1)*4
#define NPAIRS 136           // a <= b pairs (K is symmetric)
// Load-balanced column bisection: forward 82 pairs (cols 1..164),
// adjoint 44 pairs (cols 252..165). Capture at column 164.
#define FW_PAIRS 82
#define FW_CAP   (FW_PAIRS - 1)          // t == 81
#define NITF     116                     // 82+31 = 113, padded to mult of 4
#define AJ_PAIRS 44
#define AJ_CAP   (AJ_PAIRS - 1)          // k == 43
#define NITA     76                      // 44+31 = 75, padded to mult of 4

__device__ float g_K[NB * NB];
__device__ int   g_count = 0;

__global__ __launch_bounds__(128, 1)
void sig_fused_kernel(const float* __restrict__ paths, float* __restrict__ out) {
    // pack[l*65 + idx] = {c1A, c2A, c1B, c2B} for lane l (coarse rows 2l, 2l+1):
    //   idx 0 -> identity, idx 1..63 -> coarse column idx-1, idx 64 -> identity
    __shared__ float4 pack[32 * 65];                  // 33280 B
    __shared__ __align__(16) float Gs[33 * 65];       // 8580 B; later overlay S/L arrays
    __shared__ __align__(16) float Xa[TT][CC];        // 2 KB
    __shared__ __align__(16) float Xb[TT][CC];        // 2 KB
    __shared__ float s_red[4];
    __shared__ float s_extra[2];                      // {lam0row, acc} from adjoint warp
    __shared__ int   s_last;

    const int tid = threadIdx.x;

    // ---- map block -> ordered pair (a <= b) ----
    int idx = blockIdx.x;
    int a = 0;
    while (idx >= NB - a) { idx -= NB - a; ++a; }
    const int b = a + idx;

    // ---- stage the two paths: X[i][c] = paths[batch][c][i] ----
    const float* pa = paths + a * (CC * TT);
    const float* pb = paths + b * (CC * TT);
    for (int e = tid; e < CC * TT; e += 128) {
        int c = e >> 6;
        int i = e & 63;
        Xa[i][c] = pa[e];
        Xb[i][c] = pb[e];
    }
    __syncthreads();

    // Gram strip: Gs[(u-uBase)*65 + v] = exp(-||Xa_u - Xb_v||^2)
    auto fill_gram = [&](int uBase, int nRows) {
        const float4* xa4 = (const float4*)&Xa[0][0];
        const float4* xb4 = (const float4*)&Xb[0][0];
        for (int e = tid; e < nRows * 64; e += 128) {
            int ur = e >> 6, v = e & 63;
            int u  = uBase + ur;
            float4 a0 = xa4[2 * u], a1 = xa4[2 * u + 1];
            float4 b0 = xb4[2 * v], b1 = xb4[2 * v + 1];
            float d = 0.f, t;
            t = a0.x - b0.x; d = fmaf(t, t, d);
            t = a0.y - b0.y; d = fmaf(t, t, d);
            t = a0.z - b0.z; d = fmaf(t, t, d);
            t = a0.w - b0.w; d = fmaf(t, t, d);
            t = a1.x - b1.x; d = fmaf(t, t, d);
            t = a1.y - b1.y; d = fmaf(t, t, d);
            t = a1.z - b1.z; d = fmaf(t, t, d);
            t = a1.w - b1.w; d = fmaf(t, t, d);
            Gs[ur * 65 + v] = __expf(-d);
        }
    };
    // Pack builder for 16 lanes [lBase, lBase+16); Gs holds rows uBase..uBase+nRows-1
    auto build_pack = [&](int lBase, int uBase) {
        for (int e = tid; e < 16 * 65; e += 128) {
            int l  = lBase + e / 65;
            int jc = e - (e / 65) * 65;
            float4 c4 = make_float4(1.f, 1.f, 1.f, 1.f);
            if (jc >= 1 && jc <= 63) {
                int v  = jc - 1;
                int u0 = 2 * l;     if (u0 > NC - 1) u0 = NC - 1;
                int u1 = 2 * l + 1; if (u1 > NC - 1) u1 = NC - 1;
                int r0 = u0 - uBase, r1 = u1 - uBase;
                float A0 = (Gs[(r0+1)*65 + v+1] + Gs[r0*65 + v] - Gs[(r0+1)*65 + v] - Gs[r0*65 + v+1]) * (1.0f/16.0f);
                float A1 = (Gs[(r1+1)*65 + v+1] + Gs[r1*65 + v] - Gs[(r1+1)*65 + v] - Gs[r1*65 + v+1]) * (1.0f/16.0f);
                float q0 = A0 * A0 * (1.0f / 12.0f);
                float q1 = A1 * A1 * (1.0f / 12.0f);
                c4 = make_float4(1.0f + 0.5f * A0 + q0, 1.0f - q0,
                                 1.0f + 0.5f * A1 + q1, 1.0f - q1);
            }
            pack[l * 65 + jc] = c4;
        }
    };

    fill_gram(0, 33);
    __syncthreads();
    build_pack(0, 0);
    __syncthreads();
    fill_gram(32, 32);
    __syncthreads();
    build_pack(16, 32);
    __syncthreads();

    // Overlays on dead Gram strip: S2f[j] = K[j+1][164], L2f[j] = lambda[j+1] at col 164
    float* S2f = Gs;          // 256 floats
    float* L2f = Gs + 256;    // 256 floats

    const int wid = tid >> 5;
    const int l   = tid & 31;

    if (wid == 0) {
        // ---- FORWARD warp: columns 1..164 (pairs t=0..81), lane l rows 8l+1..8l+8 ----
        const float4* packL = &pack[l * 65];
        float p0=1.f,p1=1.f,p2=1.f,p3=1.f,p4=1.f,p5=1.f,p6=1.f,p7=1.f;
        float topPrev = 1.f, vlo = 1.f, vhi = 1.f;

        #pragma unroll 4
        for (int s = 0; s < NITF; ++s) {
            float tc0 = __shfl_up_sync(0xffffffffu, vlo, 1);
            float tc1 = __shfl_up_sync(0xffffffffu, vhi, 1);
            if (l == 0) { tc0 = 1.f; tc1 = 1.f; }
            int t  = s - l;                       // column pair (cols 2t+1, 2t+2)
            int ci = (t >> 1) + 1;                // coarse column + 1
            ci = ci < 0 ? 0 : (ci > 64 ? 64 : ci);
            float4 c = packL[ci];

            float h0 = fmaf(p0, c.x, -(topPrev * c.y));
            float h1 = fmaf(p1, c.x, -(p0 * c.y));
            float h2 = fmaf(p2, c.x, -(p1 * c.y));
            float h3 = fmaf(p3, c.x, -(p2 * c.y));
            float h4 = fmaf(p4, c.z, -(p3 * c.w));
            float h5 = fmaf(p5, c.z, -(p4 * c.w));
            float h6 = fmaf(p6, c.z, -(p5 * c.w));
            float h7 = fmaf(p7, c.z, -(p6 * c.w));
            float v0 = fmaf(tc0, c.x, h0);
            float v1 = fmaf(v0, c.x, h1);
            float v2 = fmaf(v1, c.x, h2);
            float v3 = fmaf(v2, c.x, h3);
            float v4 = fmaf(v3, c.z, h4);
            float v5 = fmaf(v4, c.z, h5);
            float v6 = fmaf(v5, c.z, h6);
            float v7 = fmaf(v6, c.z, h7);
            float g0 = fmaf(v0, c.x, -(tc0 * c.y));
            float g1 = fmaf(v1, c.x, -(v0 * c.y));
            float g2 = fmaf(v2, c.x, -(v1 * c.y));
            float g3 = fmaf(v3, c.x, -(v2 * c.y));
            float g4 = fmaf(v4, c.z, -(v3 * c.w));
            float g5 = fmaf(v5, c.z, -(v4 * c.w));
            float g6 = fmaf(v6, c.z, -(v5 * c.w));
            float g7 = fmaf(v7, c.z, -(v6 * c.w));
            float w0 = fmaf(tc1, c.x, g0);
            float w1 = fmaf(w0, c.x, g1);
            float w2 = fmaf(w1, c.x, g2);
            float w3 = fmaf(w2, c.x, g3);
            float w4 = fmaf(w3, c.z, g4);
            float w5 = fmaf(w4, c.z, g5);
            float w6 = fmaf(w5, c.z, g6);
            float w7 = fmaf(w6, c.z, g7);

            topPrev = tc1;
            p0=w0; p1=w1; p2=w2; p3=w3; p4=w4; p5=w5; p6=w6; p7=w7;
            vlo = v7; vhi = w7;

            if (t == FW_CAP) {                    // state = column 164
                *(float4*)&S2f[l * 8]     = make_float4(p0, p1, p2, p3);
                *(float4*)&S2f[l * 8 + 4] = make_float4(p4, p5, p6, p7);
            }
        }
    } else if (wid == 1) {
        // ---- ADJOINT warp: consumes columns 252..165 (pairs k=0..43) ----
        // lambda rows 8l+1..8l+8 in L0..L7; gamma chain runs top->down (shfl_down).
        // Per column j: gam_i = lam_i + a_{i+1} gam_{i+1}; mu_i = a_i gam_i - b_{i+1} gam_{i+1}
        // Row 0: acc += lam0row + a_1*gam_1 ; lam0row <- -b_1*gam_1.
        const float4* packL = &pack[l * 65];
        const float2* packC = (const float2*)&pack[(l < 31 ? l + 1 : 31) * 65];
        float L0=0.f,L1=0.f,L2=0.f,L3=0.f,L4=0.f,L5=0.f,L6=0.f,L7=0.f;
        if (l == 31) L3 = 1.f;                    // lambda_252 = 1
        float lam0row = 0.f, acc = 0.f;
        float gpass_hi = 0.f, gpass_lo = 0.f;

        #pragma unroll 4
        for (int s = 0; s < NITA; ++s) {
            float gin0 = __shfl_down_sync(0xffffffffu, gpass_hi, 1);
            float gin1 = __shfl_down_sync(0xffffffffu, gpass_lo, 1);
            if (l == 31) { gin0 = 0.f; gin1 = 0.f; }
            int k  = s - (31 - l);                // pair k: cols (252-2k, 251-2k)
            int ci = ((125 - k) >> 1) + 1;        // coarse column + 1
            ci = ci < 0 ? 0 : (ci > 64 ? 64 : ci);
            float4 c  = packL[ci];                // aA=c.x bA=c.y aB=c.z bB=c.w
            float2 cc = packC[ci * 2];            // aC=cc.x bC=cc.y (coarse row 2l+2)

            // ---- column hi (252-2k) ----
            float g7 = fmaf(cc.x, gin0, L7);
            float g6 = fmaf(c.z, g7, L6);
            float g5 = fmaf(c.z, g6, L5);
            float g4 = fmaf(c.z, g5, L4);
            float g3 = fmaf(c.z, g4, L3);
            float g2 = fmaf(c.x, g3, L2);
            float g1 = fmaf(c.x, g2, L1);
            float g0 = fmaf(c.x, g1, L0);
            float m7 = fmaf(c.z, g7, -(cc.y * gin0));
            float m6 = fmaf(c.z, g6, -(c.w * g7));
            float m5 = fmaf(c.z, g5, -(c.w * g6));
            float m4 = fmaf(c.z, g4, -(c.w * g5));
            float m3 = fmaf(c.x, g3, -(c.w * g4));
            float m2 = fmaf(c.x, g2, -(c.y * g3));
            float m1 = fmaf(c.x, g1, -(c.y * g2));
            float m0 = fmaf(c.x, g0, -(c.y * g1));
            if (l == 0) { acc += fmaf(c.x, g0, lam0row); lam0row = -(c.y * g0); }
            // ---- column lo (251-2k) ----
            float h7 = fmaf(cc.x, gin1, m7);
            float h6 = fmaf(c.z, h7, m6);
            float h5 = fmaf(c.z, h6, m5);
            float h4 = fmaf(c.z, h5, m4);
            float h3 = fmaf(c.z, h4, m3);
            float h2 = fmaf(c.x, h3, m2);
            float h1 = fmaf(c.x, h2, m1);
            float h0 = fmaf(c.x, h1, m0);
            float n7 = fmaf(c.z, h7, -(cc.y * gin1));
            float n6 = fmaf(c.z, h6, -(c.w * h7));
            float n5 = fmaf(c.z, h5, -(c.w * h6));
            float n4 = fmaf(c.z, h4, -(c.w * h5));
            float n3 = fmaf(c.x, h3, -(c.w * h4));
            float n2 = fmaf(c.x, h2, -(c.y * h3));
            float n1 = fmaf(c.x, h1, -(c.y * h2));
            float n0 = fmaf(c.x, h0, -(c.y * h1));
            if (l == 0) { acc += fmaf(c.x, h0, lam0row); lam0row = -(c.y * h0); }

            L0=n0; L1=n1; L2=n2; L3=n3; L4=n4; L5=n5; L6=n6; L7=n7;
            gpass_hi = g0; gpass_lo = h0;

            if (k == AJ_CAP) {                    // lambda for column 164
                *(float4*)&L2f[l * 8]     = make_float4(n0, n1, n2, n3);
                *(float4*)&L2f[l * 8 + 4] = make_float4(n4, n5, n6, n7);
                if (l == 0) { s_extra[0] = lam0row; s_extra[1] = acc; }
            }
        }
    }
    __syncthreads();

    // ---- combine: K[252][252] = sum_i L[i]*S[i] (i=1..252) + lam0row*1 + acc ----
    {
        float partial = 0.f;
        if (tid < 252)       partial  = S2f[tid] * L2f[tid];
        int j2 = tid + 128;
        if (j2 < 252)        partial += S2f[j2] * L2f[j2];
        #pragma unroll
        for (int o = 16; o; o >>= 1) partial += __shfl_xor_sync(0xffffffffu, partial, o);
        if ((tid & 31) == 0) s_red[tid >> 5] = partial;
    }
    __syncthreads();
    if (tid == 0) {
        float total = s_red[0] + s_red[1] + s_red[2] + s_red[3]
                    + s_extra[0] + s_extra[1];
        g_K[a * NB + b] = total;
        g_K[b * NB + a] = total;              // symmetry
    }
    __syncthreads();

    // ---- last block to finish does the (16,2) reduction ----
    if (tid == 0) {
        __threadfence();
        int prev = atomicAdd(&g_count, 1);
        s_last = (prev == NPAIRS - 1) ? 1 : 0;
    }
    __syncthreads();
    if (s_last) {
        __threadfence();
        if (tid < NB) {
            float sm = 0.0f;
            #pragma unroll
            for (int bb = 0; bb < NB; ++bb) sm += __ldcg(&g_K[tid * NB + bb]);
            out[2 * tid]     = __ldcg(&g_K[tid * NB + tid]);
            out[2 * tid + 1] = sm * (1.0f / (float)NB);
        }
        if (tid == 0) g_count = 0;            // reset for next graph replay
    }
}

extern "C" void kernel_launch(void* const* d_in, const int* in_sizes, int n_in,
                              void* d_out, int out_size) {
    const float* paths = (const float*)d_in[0];
    sig_fused_kernel<<<NPAIRS, 128>>>(paths, (float*)d_out);
}